// round 6
// baseline (speedup 1.0000x reference)
#include <cuda_runtime.h>
#include <cuda_bf16.h>
#include <math.h>

// ConstrativeLoss: result = (||sum_i n_i||^2 - sum_i n_i.n_i) / (N * T)
// with n_i = x_i / max(||x_i||, 1e-8). O(N D). Single launch.
// Phase 1: each warp owns exactly 4 rows; ALL 16 LDG.128 issued in a
//          straight-line prologue (2 KB in flight per warp) before any
//          consumption -> latency-hiding instead of burst-and-wait.
// Phase 2: 32 blocks spin-barrier, each sums 16 partial rows.
// Phase 3: last phase-2 block reduces 32 rows + diag -> scalar.
// Determinism: int-only atomics, all float/double sums in fixed order.

#define N_ROWS   16384
#define DIMS     512
#define NB       512
#define NT       256
#define NW       8
#define NB2      32       // phase-2 blocks
#define ROWS_PER 16       // partial rows per phase-2 block
#define TEMP     0.5
#define EPS      1e-8f

__device__ float  g_spart[NB * DIMS];     // 1 MB partials (L2-resident)
__device__ float  g_stage2[NB2 * DIMS];   // 64 KB stage-2 partials
__device__ double g_diagpart[NB];
__device__ unsigned int g_count1;         // phase1 done counter (rearmed)
__device__ unsigned int g_count2;         // phase2 done counter (rearmed)

__global__ __launch_bounds__(NT) void k_fused(const float* __restrict__ x,
                                              float* __restrict__ out) {
    __shared__ float4 s_sh4[NW * (DIMS / 4)];   // 16 KB
    __shared__ double diag_sh[NW];
    __shared__ double shv[128];
    __shared__ double shd[256];
    __shared__ bool   is_last;

    const int w = threadIdx.x >> 5;
    const int l = threadIdx.x & 31;
    const int gwarp = blockIdx.x * NW + w;
    const int nwarps = NB * NW;                 // 4096 warps, 16384/4096 = 4 rows

    // ========== phase 1: straight-line, fully front-batched loads =========
    // Rows for this warp: gwarp + r*nwarps, r = 0..3.
    float4 v[4][4];                              // 64 regs of data
#pragma unroll
    for (int r = 0; r < 4; r++) {
        const float4* xr = reinterpret_cast<const float4*>(
            x + (size_t)(gwarp + r * nwarps) * DIMS);
#pragma unroll
        for (int p = 0; p < 4; p++)
            v[r][p] = xr[p * 32 + l];            // 16 independent LDG.128
    }

    // sum of squares, 4 independent chains
    float ss[4];
#pragma unroll
    for (int r = 0; r < 4; r++) {
        float s = 0.f;
#pragma unroll
        for (int p = 0; p < 4; p++)
            s += v[r][p].x * v[r][p].x + v[r][p].y * v[r][p].y
               + v[r][p].z * v[r][p].z + v[r][p].w * v[r][p].w;
        ss[r] = s;
    }
    // interleaved butterfly reduce (4 independent SHFL chains pipeline)
#pragma unroll
    for (int o = 16; o > 0; o >>= 1) {
#pragma unroll
        for (int r = 0; r < 4; r++)
            ss[r] += __shfl_xor_sync(0xFFFFFFFFu, ss[r], o);
    }

    float inv[4];
    double diag = 0.0;
#pragma unroll
    for (int r = 0; r < 4; r++) {
        inv[r] = 1.0f / fmaxf(sqrtf(ss[r]), EPS);
        if (l == 0)
            diag += (double)(ss[r] * inv[r] * inv[r]);
    }

    float4 acc[4];
#pragma unroll
    for (int p = 0; p < 4; p++) {
        acc[p].x = v[0][p].x * inv[0] + v[1][p].x * inv[1]
                 + v[2][p].x * inv[2] + v[3][p].x * inv[3];
        acc[p].y = v[0][p].y * inv[0] + v[1][p].y * inv[1]
                 + v[2][p].y * inv[2] + v[3][p].y * inv[3];
        acc[p].z = v[0][p].z * inv[0] + v[1][p].z * inv[1]
                 + v[2][p].z * inv[2] + v[3][p].z * inv[3];
        acc[p].w = v[0][p].w * inv[0] + v[1][p].w * inv[1]
                 + v[2][p].w * inv[2] + v[3][p].w * inv[3];
    }

    // stash per-warp partials (ordered combine, deterministic)
#pragma unroll
    for (int p = 0; p < 4; p++)
        s_sh4[w * 128 + p * 32 + l] = acc[p];
    if (l == 0)
        diag_sh[w] = diag;
    __syncthreads();

    const int t = threadIdx.x;
    if (t < 128) {
        float4 sum = s_sh4[t];
#pragma unroll
        for (int ww = 1; ww < NW; ww++) {
            float4 a = s_sh4[ww * 128 + t];
            sum.x += a.x; sum.y += a.y; sum.z += a.z; sum.w += a.w;
        }
        reinterpret_cast<float4*>(g_spart + (size_t)blockIdx.x * DIMS)[t] = sum;
    }
    if (t == 0) {
        double d = 0.0;
#pragma unroll
        for (int ww = 0; ww < NW; ww++) d += diag_sh[ww];
        g_diagpart[blockIdx.x] = d;
    }

    __threadfence();
    if (t == 0) atomicAdd(&g_count1, 1u);

    // ========== phase 2: 32 blocks, 16 rows each ==========================
    if (blockIdx.x >= NB2) return;

    if (t == 0) {
        while (atomicAdd(&g_count1, 0u) < NB) { /* spin; exiting blocks free slots */ }
    }
    __syncthreads();
    __threadfence();

    if (t < 128) {
        const float4* sp = reinterpret_cast<const float4*>(g_spart);
        const int base = blockIdx.x * ROWS_PER;
        float4 pa[4];
        pa[0] = make_float4(0.f, 0.f, 0.f, 0.f);
        pa[1] = pa[0]; pa[2] = pa[0]; pa[3] = pa[0];
#pragma unroll
        for (int i = 0; i < ROWS_PER; i++) {    // 16 independent L2-hot LDG.128
            float4 a = sp[(size_t)(base + i) * 128 + t];
            pa[i & 3].x += a.x; pa[i & 3].y += a.y;
            pa[i & 3].z += a.z; pa[i & 3].w += a.w;
        }
        float4 ps;
        ps.x = (pa[0].x + pa[1].x) + (pa[2].x + pa[3].x);
        ps.y = (pa[0].y + pa[1].y) + (pa[2].y + pa[3].y);
        ps.z = (pa[0].z + pa[1].z) + (pa[2].z + pa[3].z);
        ps.w = (pa[0].w + pa[1].w) + (pa[2].w + pa[3].w);
        reinterpret_cast<float4*>(g_stage2 + (size_t)blockIdx.x * DIMS)[t] = ps;
    }

    __threadfence();
    __syncthreads();
    if (t == 0) {
        unsigned int old = atomicAdd(&g_count2, 1u);
        is_last = (old == NB2 - 1);
    }
    __syncthreads();
    if (!is_last) return;

    // ========== phase 3: final scalar =====================================
    __threadfence();
    {
        const int c4 = t & 127;          // float4 column 0..127
        const int half = t >> 7;         // 0..1 over stage-2 rows (16 each)
        const float4* sp = reinterpret_cast<const float4*>(g_stage2);

        float4 pa[4];
        pa[0] = make_float4(0.f, 0.f, 0.f, 0.f);
        pa[1] = pa[0]; pa[2] = pa[0]; pa[3] = pa[0];
#pragma unroll
        for (int i = 0; i < 16; i++) {
            int r = half * 16 + i;
            float4 a = sp[(size_t)r * 128 + c4];
            pa[i & 3].x += a.x; pa[i & 3].y += a.y;
            pa[i & 3].z += a.z; pa[i & 3].w += a.w;
        }
        float4 ps;
        ps.x = (pa[0].x + pa[1].x) + (pa[2].x + pa[3].x);
        ps.y = (pa[0].y + pa[1].y) + (pa[2].y + pa[3].y);
        ps.z = (pa[0].z + pa[1].z) + (pa[2].z + pa[3].z);
        ps.w = (pa[0].w + pa[1].w) + (pa[2].w + pa[3].w);

        s_sh4[t] = ps;                   // reuse 16 KB staging
        __syncthreads();

        if (t < 128) {                   // combine the 2 halves, fixed order
            float4 a = s_sh4[t];
            float4 b = s_sh4[128 + t];
            double sx = (double)(a.x + b.x), sy = (double)(a.y + b.y);
            double sz = (double)(a.z + b.z), sw = (double)(a.w + b.w);
            shv[t] = sx * sx + sy * sy + sz * sz + sw * sw;
        }
        // diag: 512 doubles, 2 per thread, fixed order
        shd[t] = g_diagpart[t] + g_diagpart[t + 256];
        __syncthreads();

#pragma unroll
        for (int o = 128; o > 0; o >>= 1) {
            if (t < o) shd[t] += shd[t + o];
            if (o <= 64 && t < o) shv[t] += shv[t + o];
            __syncthreads();
        }
        if (t == 0) {
            double num = shv[0] - shd[0];
            out[0] = (float)(num / ((double)N_ROWS * TEMP));
            g_count1 = 0;                // rearm for next graph replay
            g_count2 = 0;
        }
    }
}

extern "C" void kernel_launch(void* const* d_in, const int* in_sizes, int n_in,
                              void* d_out, int out_size) {
    const float* x = (const float*)d_in[0];
    float* out = (float*)d_out;
    k_fused<<<NB, NT>>>(x, out);
}

// round 9
// speedup vs baseline: 1.1089x; 1.1089x over previous
#include <cuda_runtime.h>
#include <cuda_bf16.h>
#include <math.h>
#include <stdint.h>

// ConstrativeLoss: result = (||sum_i n_i||^2 - sum_i n_i.n_i) / (N * T)
// with n_i = x_i / max(||x_i||, 1e-8). O(N D), single launch.
// Streaming via cp.async triple-buffered smem pipeline: producer (LDGSTS)
// decoupled from consumer (LDS + shfl), so bytes-in-flight = pipeline depth,
// independent of consumer stalls. 256 CTAs x 64 rows -> all 148 SMs active,
// 2 CTAs/SM where co-resident.
// Determinism: int-only atomics, all float/double sums in fixed order.

#define N_ROWS    16384
#define DIMS      512
#define NB        256          // CTAs; 16384 = 256 * 64 rows, exact
#define NT        512          // threads (16 warps)
#define NW        16
#define ROWS_CTA  64
#define STG_ROWS  16           // one row per warp per stage
#define NSTG      4            // ROWS_CTA / STG_ROWS
#define DEPTH     3            // pipeline stages resident
#define STG_F4    (STG_ROWS * DIMS / 4)   // 2048 float4 = 32 KB
#define DYN_SMEM  (DEPTH * STG_F4 * 16)   // 96 KB
#define TEMP      0.5
#define EPS       1e-8f

__device__ float  g_spart[NB * DIMS];   // 512 KB partials (L2-resident)
__device__ double g_diagpart[NB];
__device__ unsigned int g_count;        // zero-init; last block rearms

__device__ __forceinline__ uint32_t smem_u32(const void* p) {
    return (uint32_t)__cvta_generic_to_shared(p);
}

__global__ void __launch_bounds__(NT)
k_fused(const float* __restrict__ x, float* __restrict__ out) {
    extern __shared__ float4 buf[];     // DEPTH * STG_F4 float4
    __shared__ double diag_sh[NW];
    __shared__ double shv[128];
    __shared__ double shd[128];
    __shared__ bool   is_last;

    const int t = threadIdx.x;
    const int w = t >> 5;
    const int l = t & 31;
    const size_t row0 = (size_t)blockIdx.x * ROWS_CTA;

    // ---- prologue: prefetch stages 0..DEPTH-1 (32 KB each, coalesced) ----
#pragma unroll
    for (int s = 0; s < DEPTH; s++) {
        const float* src = x + (row0 + (size_t)s * STG_ROWS) * DIMS;
        uint32_t dst = smem_u32(buf + s * STG_F4);
#pragma unroll
        for (int k = 0; k < 4; k++) {
            asm volatile("cp.async.cg.shared.global [%0], [%1], 16;\n" ::
                "r"(dst + (uint32_t)(t + k * NT) * 16),
                "l"(src + (size_t)(t + k * NT) * 4) : "memory");
        }
        asm volatile("cp.async.commit_group;\n" ::: "memory");
    }

    float4 acc[4];
    acc[0] = make_float4(0.f, 0.f, 0.f, 0.f);
    acc[1] = acc[0]; acc[2] = acc[0]; acc[3] = acc[0];
    double diag = 0.0;

    // ---- mainloop over NSTG stages ----
    for (int s = 0; s < NSTG; s++) {
        // group s complete once <= DEPTH-1 groups pending (empty tail commits
        // keep the count advancing)
        asm volatile("cp.async.wait_group %0;\n" :: "n"(DEPTH - 1) : "memory");
        __syncthreads();

        // consume: warp w owns row w of this stage
        const float4* row = buf + (s % DEPTH) * STG_F4 + w * (DIMS / 4);
        float4 v[4];
#pragma unroll
        for (int p = 0; p < 4; p++)
            v[p] = row[p * 32 + l];             // conflict-free LDS.128

        float ss = 0.f;
#pragma unroll
        for (int p = 0; p < 4; p++)
            ss += v[p].x * v[p].x + v[p].y * v[p].y
                + v[p].z * v[p].z + v[p].w * v[p].w;
#pragma unroll
        for (int o = 16; o > 0; o >>= 1)
            ss += __shfl_xor_sync(0xFFFFFFFFu, ss, o);

        float inv = 1.0f / fmaxf(sqrtf(ss), EPS);
        if (l == 0) diag += (double)(ss * inv * inv);
#pragma unroll
        for (int p = 0; p < 4; p++) {
            acc[p].x += v[p].x * inv;
            acc[p].y += v[p].y * inv;
            acc[p].z += v[p].z * inv;
            acc[p].w += v[p].w * inv;
        }

        __syncthreads();                        // slot free before refill

        if (s + DEPTH < NSTG) {                 // prefetch stage s+DEPTH
            const float* src = x + (row0 + (size_t)(s + DEPTH) * STG_ROWS) * DIMS;
            uint32_t dst = smem_u32(buf + ((s + DEPTH) % DEPTH) * STG_F4);
#pragma unroll
            for (int k = 0; k < 4; k++) {
                asm volatile("cp.async.cg.shared.global [%0], [%1], 16;\n" ::
                    "r"(dst + (uint32_t)(t + k * NT) * 16),
                    "l"(src + (size_t)(t + k * NT) * 4) : "memory");
            }
        }
        asm volatile("cp.async.commit_group;\n" ::: "memory");  // may be empty
    }
    asm volatile("cp.async.wait_group 0;\n" ::: "memory");
    __syncthreads();

    // ---- block combine: reuse buf as staging (fixed order, deterministic) --
#pragma unroll
    for (int p = 0; p < 4; p++)
        buf[w * 128 + p * 32 + l] = acc[p];
    if (l == 0) diag_sh[w] = diag;
    __syncthreads();

    if (t < 128) {
        float4 sum = buf[t];
#pragma unroll
        for (int ww = 1; ww < NW; ww++) {
            float4 a = buf[ww * 128 + t];
            sum.x += a.x; sum.y += a.y; sum.z += a.z; sum.w += a.w;
        }
        reinterpret_cast<float4*>(g_spart + (size_t)blockIdx.x * DIMS)[t] = sum;
    }
    if (t == 0) {
        double d = 0.0;
#pragma unroll
        for (int ww = 0; ww < NW; ww++) d += diag_sh[ww];
        g_diagpart[blockIdx.x] = d;
    }

    __threadfence();
    __syncthreads();
    if (t == 0) {
        unsigned int old = atomicAdd(&g_count, 1u);
        is_last = (old == NB - 1);
    }
    __syncthreads();
    if (!is_last) return;

    // ---- last-block final reduction (L2-hot, fixed order) ----
    __threadfence();
    {
        const int c4 = t & 127;          // float4 column 0..127
        const int sl = t >> 7;           // 0..3 slice, 64 partial rows each
        const float4* sp = reinterpret_cast<const float4*>(g_spart);

        float4 pa[4];
        pa[0] = make_float4(0.f, 0.f, 0.f, 0.f);
        pa[1] = pa[0]; pa[2] = pa[0]; pa[3] = pa[0];
#pragma unroll
        for (int i = 0; i < 64; i++) {   // 64 independent LDG.128
            int r = sl * 64 + i;
            float4 a = sp[(size_t)r * 128 + c4];
            pa[i & 3].x += a.x; pa[i & 3].y += a.y;
            pa[i & 3].z += a.z; pa[i & 3].w += a.w;
        }
        float4 ps;
        ps.x = (pa[0].x + pa[1].x) + (pa[2].x + pa[3].x);
        ps.y = (pa[0].y + pa[1].y) + (pa[2].y + pa[3].y);
        ps.z = (pa[0].z + pa[1].z) + (pa[2].z + pa[3].z);
        ps.w = (pa[0].w + pa[1].w) + (pa[2].w + pa[3].w);

        buf[t] = ps;                     // reuse pipeline smem
        __syncthreads();

        if (t < 128) {                   // combine 4 slices in fixed order
            float4 s0 = buf[t], s1 = buf[128 + t], s2 = buf[256 + t], s3 = buf[384 + t];
            double sx = (double)(((s0.x + s1.x) + (s2.x + s3.x)));
            double sy = (double)(((s0.y + s1.y) + (s2.y + s3.y)));
            double sz = (double)(((s0.z + s1.z) + (s2.z + s3.z)));
            double sw = (double)(((s0.w + s1.w) + (s2.w + s3.w)));
            shv[t] = sx * sx + sy * sy + sz * sz + sw * sw;
            // diag: 256 doubles, 2 per thread, fixed order
            shd[t] = g_diagpart[t] + g_diagpart[t + 128];
        }
        __syncthreads();

#pragma unroll
        for (int o = 64; o > 0; o >>= 1) {
            if (t < o) {
                shv[t] += shv[t + o];
                shd[t] += shd[t + o];
            }
            __syncthreads();
        }
        if (t == 0) {
            double num = shv[0] - shd[0];
            out[0] = (float)(num / ((double)N_ROWS * TEMP));
            g_count = 0;                 // rearm for next graph replay
        }
    }
}

extern "C" void kernel_launch(void* const* d_in, const int* in_sizes, int n_in,
                              void* d_out, int out_size) {
    const float* x = (const float*)d_in[0];
    float* out = (float*)d_out;
    cudaFuncSetAttribute(k_fused, cudaFuncAttributeMaxDynamicSharedMemorySize,
                         DYN_SMEM);   // idempotent, not stream-ordered
    k_fused<<<NB, NT, DYN_SMEM>>>(x, out);
}